// round 14
// baseline (speedup 1.0000x reference)
#include <cuda_runtime.h>

#define E_EDGES 250000
#define TILE_E  64
#define NBLOCKS ((E_EDGES + TILE_E - 1) / TILE_E)
#define GRID    444   /* 3 CTAs x 148 SMs, persistent */

using u64 = unsigned long long;

__device__ float g_wsh[12288];   // pre-swizzled W image (exact smem layout)

__device__ __forceinline__ u64 ffma2(u64 a, u64 b, u64 c) {
    u64 d;
    asm("fma.rn.f32x2 %0, %1, %2, %3;" : "=l"(d) : "l"(a), "l"(b), "l"(c));
    return d;
}
__device__ __forceinline__ u64 dup2(float x) {
    u64 d;
    asm("mov.b64 %0, {%1, %1};" : "=l"(d) : "f"(x));
    return d;
}
__device__ __forceinline__ float lo32(u64 v) { return __uint_as_float((unsigned)(v & 0xffffffffu)); }
__device__ __forceinline__ float hi32(u64 v) { return __uint_as_float((unsigned)(v >> 32)); }

// W layout per (d,h): base = d*192 + h*96 floats   (h = channel half, c0 = h*32+2cp)
//   blockA [0,64):  cp*4 -> {W[c0][r0], W[c1][r0], W[c0][r1], W[c1][r1]}
//   blockB [64,96): cp*2 -> {W[c0][r2], W[c1][r2]}
__global__ void prep_w_kernel(const float* __restrict__ W) {
    int o = blockIdx.x * 256 + threadIdx.x;
    if (o < 12288) {
        int d    = o / 192;
        int rem  = o - d * 192;
        int h    = rem / 96;
        int rem2 = rem - h * 96;
        int c, r;
        if (rem2 < 64) {
            int cp = rem2 >> 2, t = rem2 & 3;
            c = h * 32 + 2 * cp + (t & 1);
            r = t >> 1;
        } else {
            int rem3 = rem2 - 64;
            int cp = rem3 >> 1;
            c = h * 32 + 2 * cp + (rem3 & 1);
            r = 2;
        }
        g_wsh[o] = W[d * 192 + c * 3 + r];
    }
}

// Shared layout (bytes):
//   wsh  : float[12288]  [0, 49152)     persistent
//   overlay [49152, 67840):  invs rows stride 68 (17408B) / epilogue stage
//            (8 warps x 584 words = 18688B)
//   shs  : float[64*12]  [67840, 70912)
#define SMEM_BYTES 70912

__device__ __forceinline__ void sh_from_vec(float x, float y, float z, float* o) {
    float r = rsqrtf(x * x + y * y + z * z);
    x *= r; y *= r; z *= r;
    const float s3  = 1.7320508075688772f;
    const float s5  = 2.2360679774997896f;
    const float s15 = 3.8729833462074170f;
    o[0] = 1.0f;
    o[1] = s3 * x;
    o[2] = s3 * y;
    o[3] = s3 * z;
    o[4] = s15 * x * z;
    o[5] = s15 * x * y;
    o[6] = s5 * (y * y - 0.5f * (x * x + z * z));
    o[7] = s15 * y * z;
    o[8] = 0.5f * s15 * (z * z - x * x);
}

__global__ __launch_bounds__(256, 3)
void sh_tensor_embed_kernel(const float* __restrict__ vec,
                            const float* __restrict__ inv,
                            float* __restrict__ out) {
    extern __shared__ char sm[];
    float* smf  = (float*)sm;
    float* invs = (float*)(sm + 49152);
    float* shs  = (float*)(sm + 67840);

    const int tid  = threadIdx.x;
    const int lane = tid & 31;
    const int wid  = tid >> 5;
    const int cp   = lane & 15;          // channel pair within half
    const int eh   = lane >> 4;          // edge octet selector (0..1)
    const int h    = wid & 1;            // channels [32h, 32h+32)
    const int g    = wid >> 1;           // edges [16g, 16g+16)

    // fill-role closed form: el = el0 + 32*(k&1), d = d0 + 8*(k>>1)
    const int el0   = (tid & 3) | ((tid >> 3) & 0x1C);
    const int d0    = (tid >> 2) & 7;
    const int sbase = d0 * 68 + el0;     // invs word offset, tile-invariant

    // ---- one-time W fill ----
    #pragma unroll
    for (int it = 0; it < 12; it++) {
        int idx = it * 256 + tid;
        ((float4*)smf)[idx] = ((const float4*)g_wsh)[idx];
    }
    // ---- fill first tile's invs + shs (first tiles are always in-range) ----
    {
        int e0 = blockIdx.x * TILE_E;
        const float* gb = inv + (size_t)(e0 + el0) * 64 + d0;
        #pragma unroll
        for (int k = 0; k < 16; k++)
            invs[sbase + (k >> 1) * 544 + (k & 1) * 32] = gb[(k & 1) * 2048 + (k >> 1) * 8];
        if (tid < TILE_E) {
            int e = e0 + tid;
            sh_from_vec(vec[(size_t)e * 3], vec[(size_t)e * 3 + 1], vec[(size_t)e * 3 + 2],
                        shs + tid * 12);
        }
    }
    __syncthreads();

    const char* wA0 = (const char*)(smf + h * 96 + cp * 4);        // LDS.128 / d
    const char* wB0 = (const char*)(smf + h * 96 + 64 + cp * 2);   // LDS.64  / d
    const float* ip0 = invs + g * 16 + eh * 8;
    float* stagew = invs + wid * 584;    // overlay (invs dead during epilogue)

    for (int tile = blockIdx.x; tile < NBLOCKS; tile += GRID) {
        const int e0 = tile * TILE_E;
        const bool full = (e0 + TILE_E <= E_EDGES);   // uniform: guard-free hot path

        // ---- mainloop: 2 channels (h*32+2cp,+1) x 8 edges ----
        u64 acc[8][3];
        #pragma unroll
        for (int j = 0; j < 8; j++)
            #pragma unroll
            for (int r = 0; r < 3; r++)
                acc[j][r] = 0ull;

        {
            const char* pa = wA0;
            const char* pb = wB0;
            const float* pi = ip0;
            #pragma unroll 2
            for (int d = 0; d < 64; d++) {
                ulonglong2 wab = *(const ulonglong2*)pa;   // {wv0, wv1}
                u64 wv2        = *(const u64*)pb;
                float iv[8];
                *(float4*)&iv[0] = *(const float4*)pi;     // broadcast LDS.128
                *(float4*)&iv[4] = *(const float4*)(pi + 4);
                #pragma unroll
                for (int j = 0; j < 8; j++) {
                    u64 pv = dup2(iv[j]);
                    acc[j][0] = ffma2(pv, wab.x, acc[j][0]);
                    acc[j][1] = ffma2(pv, wab.y, acc[j][1]);
                    acc[j][2] = ffma2(pv, wv2,   acc[j][2]);
                }
                pa += 768; pb += 768; pi += 68;
            }
        }
        __syncthreads();                 // invs reads done -> stage overlay safe

        // ---- prefetch next tile while epilogue runs ----
        const int nt = tile + GRID;
        const bool nxt = nt < NBLOCKS;
        float pv[16];
        float vx = 0.f, vy = 0.f, vz = 0.f;
        if (nxt) {
            int ne0 = nt * TILE_E;
            if (nt < NBLOCKS - 1) {      // uniform: clamp-free hot path
                const float* gb = inv + (size_t)(ne0 + el0) * 64 + d0;
                #pragma unroll
                for (int k = 0; k < 16; k++)
                    pv[k] = gb[(k & 1) * 2048 + (k >> 1) * 8];
                if (tid < TILE_E) {
                    int e = ne0 + tid;
                    vx = vec[(size_t)e * 3];
                    vy = vec[(size_t)e * 3 + 1];
                    vz = vec[(size_t)e * 3 + 2];
                }
            } else {                     // last tile: clamp (OOB otherwise)
                #pragma unroll
                for (int k = 0; k < 16; k++) {
                    int el = el0 + 32 * (k & 1);
                    int d  = d0 + 8 * (k >> 1);
                    int e = ne0 + el; if (e >= E_EDGES) e = E_EDGES - 1;
                    pv[k] = inv[(size_t)e * 64 + d];
                }
                if (tid < TILE_E) {
                    int e = ne0 + tid; if (e >= E_EDGES) e = E_EDGES - 1;
                    vx = vec[(size_t)e * 3];
                    vy = vec[(size_t)e * 3 + 1];
                    vz = vec[(size_t)e * 3 + 2];
                }
            }
        }

        // ---- epilogue: 8 rounds; stage 2 edges/round, coalesced copy-out ----
        #pragma unroll
        for (int s = 0; s < 8; s++) {
            {
                int el = g * 16 + eh * 8 + s;
                const float* sb = shs + el * 12;
                float4 sa  = *(const float4*)sb;
                float4 sbv = *(const float4*)(sb + 4);
                float  s8  = sb[8];
                float sv[9] = {sa.x, sa.y, sa.z, sa.w, sbv.x, sbv.y, sbv.z, sbv.w, s8};
                float wa[3], wb[3];
                #pragma unroll
                for (int r = 0; r < 3; r++) { wa[r] = lo32(acc[s][r]); wb[r] = hi32(acc[s][r]); }
                float v[18];
                #pragma unroll
                for (int k = 0; k < 9; k++) {
                    int r = (k == 0) ? 0 : ((k < 4) ? 1 : 2);
                    v[k]     = sv[k] * wa[r];
                    v[9 + k] = sv[k] * wb[r];
                }
                float* rowp = stagew + eh * 292 + cp * 18;
                #pragma unroll
                for (int p = 0; p < 9; p++)
                    *(float2*)(rowp + 2 * p) = make_float2(v[2 * p], v[2 * p + 1]);
            }
            __syncwarp();
            if (full) {
                #pragma unroll
                for (int t = 0; t < 2; t++) {
                    int e = e0 + g * 16 + t * 8 + s;
                    const float4* src = (const float4*)(stagew + t * 292);
                    float4* dst = (float4*)(out + (size_t)e * 576 + h * 288);
                    dst[lane]      = src[lane];
                    dst[lane + 32] = src[lane + 32];
                    if (lane < 8) dst[lane + 64] = src[lane + 64];
                }
            } else {
                #pragma unroll
                for (int t = 0; t < 2; t++) {
                    int e = e0 + g * 16 + t * 8 + s;
                    if (e < E_EDGES) {
                        const float4* src = (const float4*)(stagew + t * 292);
                        float4* dst = (float4*)(out + (size_t)e * 576 + h * 288);
                        dst[lane]      = src[lane];
                        dst[lane + 32] = src[lane + 32];
                        if (lane < 8) dst[lane + 64] = src[lane + 64];
                    }
                }
            }
            __syncwarp();
        }
        __syncthreads();                 // stage reads done -> invs refill safe

        // ---- commit prefetched tile (conflict-free STS, immediate offsets) ----
        if (nxt) {
            #pragma unroll
            for (int k = 0; k < 16; k++)
                invs[sbase + (k >> 1) * 544 + (k & 1) * 32] = pv[k];
            if (tid < TILE_E)
                sh_from_vec(vx, vy, vz, shs + tid * 12);
        }
        __syncthreads();
    }
}

extern "C" void kernel_launch(void* const* d_in, const int* in_sizes, int n_in,
                              void* d_out, int out_size) {
    const float* vec = nullptr;
    const float* inv = nullptr;
    const float* W   = nullptr;
    for (int i = 0; i < n_in; i++) {
        if      (in_sizes[i] == E_EDGES * 3)  vec = (const float*)d_in[i];
        else if (in_sizes[i] == E_EDGES * 64) inv = (const float*)d_in[i];
        else if (in_sizes[i] == 64 * 192)     W   = (const float*)d_in[i];
    }
    prep_w_kernel<<<48, 256>>>(W);
    cudaFuncSetAttribute(sh_tensor_embed_kernel,
                         cudaFuncAttributeMaxDynamicSharedMemorySize, SMEM_BYTES);
    sh_tensor_embed_kernel<<<GRID, 256, SMEM_BYTES>>>(vec, inv, (float*)d_out);
}

// round 15
// speedup vs baseline: 1.0973x; 1.0973x over previous
#include <cuda_runtime.h>

#define E_EDGES 250000
#define TILE_E  64
#define NBLOCKS ((E_EDGES + TILE_E - 1) / TILE_E)
#define GRID    444   /* 3 CTAs x 148 SMs, persistent */

using u64 = unsigned long long;

__device__ float g_wsh[12288];   // pre-swizzled W image (exact smem layout)
__device__ int   g_tile_ctr;     // dynamic tile counter (reset each launch)

__device__ __forceinline__ u64 ffma2(u64 a, u64 b, u64 c) {
    u64 d;
    asm("fma.rn.f32x2 %0, %1, %2, %3;" : "=l"(d) : "l"(a), "l"(b), "l"(c));
    return d;
}
__device__ __forceinline__ u64 dup2(float x) {
    u64 d;
    asm("mov.b64 %0, {%1, %1};" : "=l"(d) : "f"(x));
    return d;
}
__device__ __forceinline__ float lo32(u64 v) { return __uint_as_float((unsigned)(v & 0xffffffffu)); }
__device__ __forceinline__ float hi32(u64 v) { return __uint_as_float((unsigned)(v >> 32)); }

// W layout per (d,h): base = d*192 + h*96 floats   (h = channel half, c0 = h*32+2cp)
//   blockA [0,64):  cp*4 -> {W[c0][r0], W[c1][r0], W[c0][r1], W[c1][r1]}
//   blockB [64,96): cp*2 -> {W[c0][r2], W[c1][r2]}
__global__ void prep_w_kernel(const float* __restrict__ W) {
    int o = blockIdx.x * 256 + threadIdx.x;
    if (o == 0) g_tile_ctr = GRID;       // first GRID tiles handed out statically
    if (o < 12288) {
        int d    = o / 192;
        int rem  = o - d * 192;
        int h    = rem / 96;
        int rem2 = rem - h * 96;
        int c, r;
        if (rem2 < 64) {
            int cp = rem2 >> 2, t = rem2 & 3;
            c = h * 32 + 2 * cp + (t & 1);
            r = t >> 1;
        } else {
            int rem3 = rem2 - 64;
            int cp = rem3 >> 1;
            c = h * 32 + 2 * cp + (rem3 & 1);
            r = 2;
        }
        g_wsh[o] = W[d * 192 + c * 3 + r];
    }
}

// Shared layout (bytes):
//   wsh  : float[12288]  [0, 49152)     persistent
//   overlay [49152, 67840):  invs rows stride 68 (17408B) / epilogue stage
//            (8 warps x 584 words = 18688B)
//   shs  : float[64*12]  [67840, 70912)
//   ntile: int           [70912, 70916)
#define SMEM_BYTES 70928

__device__ __forceinline__ void sh_from_vec(float x, float y, float z, float* o) {
    float r = rsqrtf(x * x + y * y + z * z);
    x *= r; y *= r; z *= r;
    const float s3  = 1.7320508075688772f;
    const float s5  = 2.2360679774997896f;
    const float s15 = 3.8729833462074170f;
    o[0] = 1.0f;
    o[1] = s3 * x;
    o[2] = s3 * y;
    o[3] = s3 * z;
    o[4] = s15 * x * z;
    o[5] = s15 * x * y;
    o[6] = s5 * (y * y - 0.5f * (x * x + z * z));
    o[7] = s15 * y * z;
    o[8] = 0.5f * s15 * (z * z - x * x);
}

__global__ __launch_bounds__(256, 3)
void sh_tensor_embed_kernel(const float* __restrict__ vec,
                            const float* __restrict__ inv,
                            float* __restrict__ out) {
    extern __shared__ char sm[];
    float* smf  = (float*)sm;
    float* invs = (float*)(sm + 49152);
    float* shs  = (float*)(sm + 67840);
    int*   ntile_sh = (int*)(sm + 70912);

    const int tid  = threadIdx.x;
    const int lane = tid & 31;
    const int wid  = tid >> 5;
    const int cp   = lane & 15;          // channel pair within half
    const int eh   = lane >> 4;          // edge octet selector (0..1)
    const int h    = wid & 1;            // channels [32h, 32h+32)
    const int g    = wid >> 1;           // edges [16g, 16g+16)

    // fill-role closed form: el = el0 + 32*(k&1), d = d0 + 8*(k>>1)
    const int el0   = (tid & 3) | ((tid >> 3) & 0x1C);
    const int d0    = (tid >> 2) & 7;
    const int sbase = d0 * 68 + el0;     // invs word offset, tile-invariant

    // ---- one-time W fill ----
    #pragma unroll
    for (int it = 0; it < 12; it++) {
        int idx = it * 256 + tid;
        ((float4*)smf)[idx] = ((const float4*)g_wsh)[idx];
    }
    // ---- fill first (static) tile's invs + shs: tiles 0..443 are always full ----
    int tile = blockIdx.x;
    {
        int e0 = tile * TILE_E;
        const float* gb = inv + (size_t)(e0 + el0) * 64 + d0;
        #pragma unroll
        for (int k = 0; k < 16; k++)
            invs[sbase + (k >> 1) * 544 + (k & 1) * 32] = gb[(k & 1) * 2048 + (k >> 1) * 8];
        if (tid < TILE_E) {
            int e = e0 + tid;
            sh_from_vec(vec[(size_t)e * 3], vec[(size_t)e * 3 + 1], vec[(size_t)e * 3 + 2],
                        shs + tid * 12);
        }
    }
    __syncthreads();

    const char* wA0 = (const char*)(smf + h * 96 + cp * 4);        // LDS.128 / d
    const char* wB0 = (const char*)(smf + h * 96 + 64 + cp * 2);   // LDS.64  / d
    const float* ip0 = invs + g * 16 + eh * 8;
    float* stagew = invs + wid * 584;    // overlay (invs dead during epilogue)

    while (tile < NBLOCKS) {
        const int e0 = tile * TILE_E;
        const bool full = (e0 + TILE_E <= E_EDGES);   // uniform: guard-free hot path

        // grab NEXT tile id early; ATOMG latency hides under the mainloop
        if (tid == 0)
            *ntile_sh = atomicAdd(&g_tile_ctr, 1);

        // ---- mainloop: 2 channels (h*32+2cp,+1) x 8 edges ----
        u64 acc[8][3];
        #pragma unroll
        for (int j = 0; j < 8; j++)
            #pragma unroll
            for (int r = 0; r < 3; r++)
                acc[j][r] = 0ull;

        {
            const char* pa = wA0;
            const char* pb = wB0;
            const float* pi = ip0;
            #pragma unroll 2
            for (int d = 0; d < 64; d++) {
                ulonglong2 wab = *(const ulonglong2*)pa;   // {wv0, wv1}
                u64 wv2        = *(const u64*)pb;
                float iv[8];
                *(float4*)&iv[0] = *(const float4*)pi;     // broadcast LDS.128
                *(float4*)&iv[4] = *(const float4*)(pi + 4);
                #pragma unroll
                for (int j = 0; j < 8; j++) {
                    u64 pv = dup2(iv[j]);
                    acc[j][0] = ffma2(pv, wab.x, acc[j][0]);
                    acc[j][1] = ffma2(pv, wab.y, acc[j][1]);
                    acc[j][2] = ffma2(pv, wv2,   acc[j][2]);
                }
                pa += 768; pb += 768; pi += 68;
            }
        }
        __syncthreads();                 // invs reads done -> stage overlay safe;
                                         // also publishes *ntile_sh
        const int nt = *ntile_sh;
        const bool nxt = nt < NBLOCKS;

        // ---- prefetch next tile while epilogue runs ----
        float pv[16];
        float vx = 0.f, vy = 0.f, vz = 0.f;
        if (nxt) {
            int ne0 = nt * TILE_E;
            if (nt < NBLOCKS - 1) {      // uniform: clamp-free hot path
                const float* gb = inv + (size_t)(ne0 + el0) * 64 + d0;
                #pragma unroll
                for (int k = 0; k < 16; k++)
                    pv[k] = gb[(k & 1) * 2048 + (k >> 1) * 8];
                if (tid < TILE_E) {
                    int e = ne0 + tid;
                    vx = vec[(size_t)e * 3];
                    vy = vec[(size_t)e * 3 + 1];
                    vz = vec[(size_t)e * 3 + 2];
                }
            } else {                     // last tile: clamp (OOB otherwise)
                #pragma unroll
                for (int k = 0; k < 16; k++) {
                    int el = el0 + 32 * (k & 1);
                    int d  = d0 + 8 * (k >> 1);
                    int e = ne0 + el; if (e >= E_EDGES) e = E_EDGES - 1;
                    pv[k] = inv[(size_t)e * 64 + d];
                }
                if (tid < TILE_E) {
                    int e = ne0 + tid; if (e >= E_EDGES) e = E_EDGES - 1;
                    vx = vec[(size_t)e * 3];
                    vy = vec[(size_t)e * 3 + 1];
                    vz = vec[(size_t)e * 3 + 2];
                }
            }
        }

        // ---- epilogue: 8 rounds; stage 2 edges/round, coalesced copy-out ----
        #pragma unroll
        for (int s = 0; s < 8; s++) {
            {
                int el = g * 16 + eh * 8 + s;
                const float* sb = shs + el * 12;
                float4 sa  = *(const float4*)sb;
                float4 sbv = *(const float4*)(sb + 4);
                float  s8  = sb[8];
                float sv[9] = {sa.x, sa.y, sa.z, sa.w, sbv.x, sbv.y, sbv.z, sbv.w, s8};
                float wa[3], wb[3];
                #pragma unroll
                for (int r = 0; r < 3; r++) { wa[r] = lo32(acc[s][r]); wb[r] = hi32(acc[s][r]); }
                float v[18];
                #pragma unroll
                for (int k = 0; k < 9; k++) {
                    int r = (k == 0) ? 0 : ((k < 4) ? 1 : 2);
                    v[k]     = sv[k] * wa[r];
                    v[9 + k] = sv[k] * wb[r];
                }
                float* rowp = stagew + eh * 292 + cp * 18;
                #pragma unroll
                for (int p = 0; p < 9; p++)
                    *(float2*)(rowp + 2 * p) = make_float2(v[2 * p], v[2 * p + 1]);
            }
            __syncwarp();
            if (full) {
                #pragma unroll
                for (int t = 0; t < 2; t++) {
                    int e = e0 + g * 16 + t * 8 + s;
                    const float4* src = (const float4*)(stagew + t * 292);
                    float4* dst = (float4*)(out + (size_t)e * 576 + h * 288);
                    dst[lane]      = src[lane];
                    dst[lane + 32] = src[lane + 32];
                    if (lane < 8) dst[lane + 64] = src[lane + 64];
                }
            } else {
                #pragma unroll
                for (int t = 0; t < 2; t++) {
                    int e = e0 + g * 16 + t * 8 + s;
                    if (e < E_EDGES) {
                        const float4* src = (const float4*)(stagew + t * 292);
                        float4* dst = (float4*)(out + (size_t)e * 576 + h * 288);
                        dst[lane]      = src[lane];
                        dst[lane + 32] = src[lane + 32];
                        if (lane < 8) dst[lane + 64] = src[lane + 64];
                    }
                }
            }
            __syncwarp();
        }
        __syncthreads();                 // stage reads done -> invs refill safe

        // ---- commit prefetched tile (conflict-free STS, immediate offsets) ----
        if (nxt) {
            #pragma unroll
            for (int k = 0; k < 16; k++)
                invs[sbase + (k >> 1) * 544 + (k & 1) * 32] = pv[k];
            if (tid < TILE_E)
                sh_from_vec(vx, vy, vz, shs + tid * 12);
        }
        __syncthreads();
        tile = nt;
    }
}

extern "C" void kernel_launch(void* const* d_in, const int* in_sizes, int n_in,
                              void* d_out, int out_size) {
    const float* vec = nullptr;
    const float* inv = nullptr;
    const float* W   = nullptr;
    for (int i = 0; i < n_in; i++) {
        if      (in_sizes[i] == E_EDGES * 3)  vec = (const float*)d_in[i];
        else if (in_sizes[i] == E_EDGES * 64) inv = (const float*)d_in[i];
        else if (in_sizes[i] == 64 * 192)     W   = (const float*)d_in[i];
    }
    prep_w_kernel<<<48, 256>>>(W);
    cudaFuncSetAttribute(sh_tensor_embed_kernel,
                         cudaFuncAttributeMaxDynamicSharedMemorySize, SMEM_BYTES);
    sh_tensor_embed_kernel<<<GRID, 256, SMEM_BYTES>>>(vec, inv, (float*)d_out);
}